// round 1
// baseline (speedup 1.0000x reference)
#include <cuda_runtime.h>
#include <math.h>

#define MROWS 4096
#define DMODEL 1024
#define QPROJ 512
#define KVPROJ 1024
#define NH 16
#define DH 64
#define SEQ 2048
#define BATCH 2
#define EPS 1e-5f

// ---------------- scratch (no allocations allowed) ----------------
__device__ float g_xq  [MROWS * DMODEL];
__device__ float g_xkv [MROWS * DMODEL];
__device__ float g_tq  [MROWS * QPROJ];
__device__ float g_cq  [MROWS * QPROJ];
__device__ float g_Q   [MROWS * DMODEL];
__device__ float g_tkv [MROWS * KVPROJ];
__device__ float g_ckv [MROWS * KVPROJ];
__device__ float g_KV  [MROWS * 2 * DMODEL];
__device__ float g_attn[MROWS * DMODEL];

// ---------------- block reduction (sum, sumsq), 256 threads ----------------
__device__ __forceinline__ float2 block_reduce2(float s, float q, float* sh) {
    #pragma unroll
    for (int o = 16; o; o >>= 1) {
        s += __shfl_xor_sync(0xffffffffu, s, o);
        q += __shfl_xor_sync(0xffffffffu, q, o);
    }
    int w = threadIdx.x >> 5;
    if ((threadIdx.x & 31) == 0) { sh[w] = s; sh[8 + w] = q; }
    __syncthreads();
    if (threadIdx.x < 32) {
        s = (threadIdx.x < 8) ? sh[threadIdx.x] : 0.f;
        q = (threadIdx.x < 8) ? sh[8 + threadIdx.x] : 0.f;
        #pragma unroll
        for (int o = 4; o; o >>= 1) {
            s += __shfl_xor_sync(0xffffffffu, s, o);
            q += __shfl_xor_sync(0xffffffffu, q, o);
        }
        if (threadIdx.x == 0) { sh[16] = s; sh[17] = q; }
    }
    __syncthreads();
    return make_float2(sh[16], sh[17]);
}

// ---------------- fused dual pre-LN: shares mu/var across both LNs ----------
__global__ void __launch_bounds__(256) prenorm_kernel(
    const float* __restrict__ x,
    const float* __restrict__ pg, const float* __restrict__ pb,
    const float* __restrict__ kg, const float* __restrict__ kb,
    float* __restrict__ xq, float* __restrict__ xkv)
{
    __shared__ float sh[18];
    int row = blockIdx.x;
    const float* xr = x + (size_t)row * DMODEL;
    float s = 0.f, q = 0.f;
    #pragma unroll
    for (int i = threadIdx.x; i < DMODEL; i += 256) { float v = xr[i]; s += v; q += v * v; }
    float2 r = block_reduce2(s, q, sh);
    float mu = r.x * (1.f / DMODEL);
    float var = r.y * (1.f / DMODEL) - mu * mu;
    float inv = rsqrtf(var + EPS);
    #pragma unroll
    for (int i = threadIdx.x; i < DMODEL; i += 256) {
        float n = (xr[i] - mu) * inv;
        xq [(size_t)row * DMODEL + i] = n * pg[i] + pb[i];
        xkv[(size_t)row * DMODEL + i] = n * kg[i] + kb[i];
    }
}

// ---------------- generic row LN ----------------
__global__ void __launch_bounds__(256) ln_kernel(
    const float* __restrict__ x, const float* __restrict__ g,
    const float* __restrict__ b, float* __restrict__ y, int N)
{
    __shared__ float sh[18];
    int row = blockIdx.x;
    const float* xr = x + (size_t)row * N;
    float s = 0.f, q = 0.f;
    for (int i = threadIdx.x; i < N; i += 256) { float v = xr[i]; s += v; q += v * v; }
    float2 r = block_reduce2(s, q, sh);
    float mu = r.x / N;
    float var = r.y / N - mu * mu;
    float inv = rsqrtf(var + EPS);
    for (int i = threadIdx.x; i < N; i += 256)
        y[(size_t)row * N + i] = (xr[i] - mu) * inv * g[i] + b[i];
}

// ---------------- tiled fp32 GEMM: C[M,N] = alpha * A[M,K] @ (B or B^T) ------
// BM=BN=64, BK=16, 256 threads, each thread 4x4. All dims multiples of 64/16.
template <bool TB>
__global__ void __launch_bounds__(256) gemm_kernel(
    const float* __restrict__ A, const float* __restrict__ B,
    float* __restrict__ C, int N, int K, float alpha)
{
    __shared__ __align__(16) float As[16][64];
    __shared__ __align__(16) float Bs[16][64];
    int tid = threadIdx.x;
    int tx = tid & 15, ty = tid >> 4;
    int m0 = blockIdx.y * 64, n0 = blockIdx.x * 64;

    float acc[4][4] = {};

    for (int k0 = 0; k0 < K; k0 += 16) {
        {   // A tile 64x16, transposed store -> As[k][m]
            int r = tid >> 2, c4 = tid & 3;
            float4 av = *(const float4*)&A[(size_t)(m0 + r) * K + k0 + c4 * 4];
            As[c4 * 4 + 0][r] = av.x; As[c4 * 4 + 1][r] = av.y;
            As[c4 * 4 + 2][r] = av.z; As[c4 * 4 + 3][r] = av.w;
        }
        if (!TB) { // B tile 16x64 direct
            int r = tid >> 4, c4 = tid & 15;
            float4 bv = *(const float4*)&B[(size_t)(k0 + r) * N + n0 + c4 * 4];
            *(float4*)&Bs[r][c4 * 4] = bv;
        } else {   // B is [N,K], transpose while loading -> Bs[k][n]
            int n = tid >> 2, c4 = tid & 3;
            float4 bv = *(const float4*)&B[(size_t)(n0 + n) * K + k0 + c4 * 4];
            Bs[c4 * 4 + 0][n] = bv.x; Bs[c4 * 4 + 1][n] = bv.y;
            Bs[c4 * 4 + 2][n] = bv.z; Bs[c4 * 4 + 3][n] = bv.w;
        }
        __syncthreads();
        #pragma unroll
        for (int k = 0; k < 16; k++) {
            float4 a = *(float4*)&As[k][ty * 4];
            float4 b = *(float4*)&Bs[k][tx * 4];
            acc[0][0] += a.x * b.x; acc[0][1] += a.x * b.y; acc[0][2] += a.x * b.z; acc[0][3] += a.x * b.w;
            acc[1][0] += a.y * b.x; acc[1][1] += a.y * b.y; acc[1][2] += a.y * b.z; acc[1][3] += a.y * b.w;
            acc[2][0] += a.z * b.x; acc[2][1] += a.z * b.y; acc[2][2] += a.z * b.z; acc[2][3] += a.z * b.w;
            acc[3][0] += a.w * b.x; acc[3][1] += a.w * b.y; acc[3][2] += a.w * b.z; acc[3][3] += a.w * b.w;
        }
        __syncthreads();
    }
    #pragma unroll
    for (int i = 0; i < 4; i++)
        #pragma unroll
        for (int j = 0; j < 4; j++)
            C[(size_t)(m0 + ty * 4 + i) * N + n0 + tx * 4 + j] = alpha * acc[i][j];
}

// ---------------- causal flash attention, 64-query tiles, fp32 --------------
// Q already scaled by 1/sqrt(dh). KP buffer doubles as K^T (during scores) and P (during PV).
__global__ void __launch_bounds__(256) attn_kernel(
    const float* __restrict__ Q, const float* __restrict__ KV, float* __restrict__ O)
{
    __shared__ __align__(16) float Qs[64][64]; // [d][row]
    __shared__ __align__(16) float KP[64][64]; // K: [d][col] ; P: [row][k]
    __shared__ __align__(16) float Vs[64][64]; // [k][d]

    int tid = threadIdx.x;
    int tx = tid & 15, ty = tid >> 4;
    int qt = blockIdx.x, h = blockIdx.y, b = blockIdx.z;

    // load Q tile (transposed into smem)
    #pragma unroll
    for (int it = 0; it < 4; it++) {
        int idx = tid + it * 256;
        int r = idx >> 4, d4 = idx & 15;
        float4 qv = *(const float4*)&Q[((size_t)(b * SEQ + qt * 64 + r)) * DMODEL + h * DH + d4 * 4];
        Qs[d4 * 4 + 0][r] = qv.x; Qs[d4 * 4 + 1][r] = qv.y;
        Qs[d4 * 4 + 2][r] = qv.z; Qs[d4 * 4 + 3][r] = qv.w;
    }

    float m[4], l[4], o[4][4];
    #pragma unroll
    for (int i = 0; i < 4; i++) {
        m[i] = -INFINITY; l[i] = 0.f;
        #pragma unroll
        for (int j = 0; j < 4; j++) o[i][j] = 0.f;
    }
    __syncthreads();

    for (int ch = 0; ch <= qt; ch++) {
        // load K (transposed) and V (direct)
        #pragma unroll
        for (int it = 0; it < 4; it++) {
            int idx = tid + it * 256;
            int r = idx >> 4, d4 = idx & 15;
            size_t base = ((size_t)(b * SEQ + ch * 64 + r)) * (2 * DMODEL) + h * DH + d4 * 4;
            float4 kv = *(const float4*)&KV[base];
            KP[d4 * 4 + 0][r] = kv.x; KP[d4 * 4 + 1][r] = kv.y;
            KP[d4 * 4 + 2][r] = kv.z; KP[d4 * 4 + 3][r] = kv.w;
            float4 vv = *(const float4*)&KV[base + DMODEL];
            *(float4*)&Vs[r][d4 * 4] = vv;
        }
        __syncthreads();

        // scores S = Q K^T  (4x4 per thread)
        float s[4][4] = {};
        #pragma unroll
        for (int d = 0; d < 64; d++) {
            float4 a = *(float4*)&Qs[d][ty * 4];
            float4 k = *(float4*)&KP[d][tx * 4];
            s[0][0] += a.x * k.x; s[0][1] += a.x * k.y; s[0][2] += a.x * k.z; s[0][3] += a.x * k.w;
            s[1][0] += a.y * k.x; s[1][1] += a.y * k.y; s[1][2] += a.y * k.z; s[1][3] += a.y * k.w;
            s[2][0] += a.z * k.x; s[2][1] += a.z * k.y; s[2][2] += a.z * k.z; s[2][3] += a.z * k.w;
            s[3][0] += a.w * k.x; s[3][1] += a.w * k.y; s[3][2] += a.w * k.z; s[3][3] += a.w * k.w;
        }

        // causal mask (only the diagonal chunk needs it)
        if (ch == qt) {
            #pragma unroll
            for (int i = 0; i < 4; i++)
                #pragma unroll
                for (int j = 0; j < 4; j++)
                    if (tx * 4 + j > ty * 4 + i) s[i][j] = -1e30f;
        }

        // online softmax: row max across the 16 tx-lanes (same half-warp group)
        float li[4], sc[4];
        #pragma unroll
        for (int i = 0; i < 4; i++) {
            float mi = fmaxf(fmaxf(s[i][0], s[i][1]), fmaxf(s[i][2], s[i][3]));
            #pragma unroll
            for (int off = 8; off; off >>= 1)
                mi = fmaxf(mi, __shfl_xor_sync(0xffffffffu, mi, off));
            float mn = fmaxf(m[i], mi);
            sc[i] = __expf(m[i] - mn);
            m[i] = mn;
            float acc = 0.f;
            #pragma unroll
            for (int j = 0; j < 4; j++) { s[i][j] = __expf(s[i][j] - mn); acc += s[i][j]; }
            #pragma unroll
            for (int off = 8; off; off >>= 1)
                acc += __shfl_xor_sync(0xffffffffu, acc, off);
            li[i] = acc;
            l[i] = l[i] * sc[i] + li[i];
            #pragma unroll
            for (int j = 0; j < 4; j++) o[i][j] *= sc[i];
        }

        __syncthreads();            // everyone done reading KP as K
        #pragma unroll
        for (int i = 0; i < 4; i++)
            #pragma unroll
            for (int j = 0; j < 4; j++)
                KP[ty * 4 + i][tx * 4 + j] = s[i][j];   // P tile, [row][k]
        __syncthreads();

        // O += P @ V
        #pragma unroll
        for (int k = 0; k < 64; k++) {
            float4 v = *(float4*)&Vs[k][tx * 4];
            #pragma unroll
            for (int i = 0; i < 4; i++) {
                float p = KP[ty * 4 + i][k];
                o[i][0] += p * v.x; o[i][1] += p * v.y;
                o[i][2] += p * v.z; o[i][3] += p * v.w;
            }
        }
        __syncthreads();            // before next chunk overwrites KP/Vs
    }

    #pragma unroll
    for (int i = 0; i < 4; i++) {
        float inv = 1.f / l[i];
        #pragma unroll
        for (int j = 0; j < 4; j++)
            O[((size_t)(b * SEQ + qt * 64 + ty * 4 + i)) * DMODEL + h * DH + tx * 4 + j] = o[i][j] * inv;
    }
}

// ---------------- launch ----------------
extern "C" void kernel_launch(void* const* d_in, const int* in_sizes, int n_in,
                              void* d_out, int out_size)
{
    const float* x     = (const float*)d_in[0];
    const float* W_dq  = (const float*)d_in[1];
    const float* W_uq  = (const float*)d_in[2];
    const float* q_g   = (const float*)d_in[3];
    const float* q_b   = (const float*)d_in[4];
    const float* W_dkv = (const float*)d_in[5];
    const float* W_ukv = (const float*)d_in[6];
    const float* kv_g  = (const float*)d_in[7];
    const float* kv_b  = (const float*)d_in[8];
    const float* pq_g  = (const float*)d_in[9];
    const float* pq_b  = (const float*)d_in[10];
    const float* pk_g  = (const float*)d_in[11];
    const float* pk_b  = (const float*)d_in[12];
    const float* wo    = (const float*)d_in[13];
    float* out = (float*)d_out;

    float *xq, *xkv, *tq, *cq, *Qp, *tkv, *ckv, *KV, *attn;
    cudaGetSymbolAddress((void**)&xq,   g_xq);
    cudaGetSymbolAddress((void**)&xkv,  g_xkv);
    cudaGetSymbolAddress((void**)&tq,   g_tq);
    cudaGetSymbolAddress((void**)&cq,   g_cq);
    cudaGetSymbolAddress((void**)&Qp,   g_Q);
    cudaGetSymbolAddress((void**)&tkv,  g_tkv);
    cudaGetSymbolAddress((void**)&ckv,  g_ckv);
    cudaGetSymbolAddress((void**)&KV,   g_KV);
    cudaGetSymbolAddress((void**)&attn, g_attn);

    // 1. fused dual pre-LN (shared mean/var)
    prenorm_kernel<<<MROWS, 256>>>(x, pq_g, pq_b, pk_g, pk_b, xq, xkv);
    // 2-4. Q path
    gemm_kernel<false><<<dim3(QPROJ / 64, MROWS / 64), 256>>>(xq, W_dq, tq, QPROJ, DMODEL, 1.f);
    ln_kernel<<<MROWS, 256>>>(tq, q_g, q_b, cq, QPROJ);
    gemm_kernel<false><<<dim3(DMODEL / 64, MROWS / 64), 256>>>(cq, W_uq, Qp, DMODEL, QPROJ, 0.125f);
    // 5-7. KV path
    gemm_kernel<false><<<dim3(KVPROJ / 64, MROWS / 64), 256>>>(xkv, W_dkv, tkv, KVPROJ, DMODEL, 1.f);
    ln_kernel<<<MROWS, 256>>>(tkv, kv_g, kv_b, ckv, KVPROJ);
    gemm_kernel<false><<<dim3(2 * DMODEL / 64, MROWS / 64), 256>>>(ckv, W_ukv, KV, 2 * DMODEL, KVPROJ, 1.f);
    // 8. causal flash attention
    attn_kernel<<<dim3(SEQ / 64, NH, BATCH), 256>>>(Qp, KV, attn);
    // 9. output projection: attn @ wo^T
    gemm_kernel<true><<<dim3(DMODEL / 64, MROWS / 64), 256>>>(attn, wo, out, DMODEL, DMODEL, 1.f);
}

// round 2
// speedup vs baseline: 2.9634x; 2.9634x over previous
#include <cuda_runtime.h>
#include <math.h>

#define MROWS 4096
#define DMODEL 1024
#define QPROJ 512
#define KVPROJ 1024
#define NH 16
#define DH 64
#define SEQ 2048
#define BATCH 2
#define EPS 1e-5f

// ---------------- scratch (no allocations allowed) ----------------
__device__ float g_xq  [MROWS * DMODEL];
__device__ float g_xkv [MROWS * DMODEL];
__device__ float g_tq  [MROWS * QPROJ];
__device__ float g_cq  [MROWS * QPROJ];
__device__ float g_Q   [MROWS * DMODEL];
__device__ float g_tkv [MROWS * KVPROJ];
__device__ float g_ckv [MROWS * KVPROJ];
__device__ float g_KV  [MROWS * 2 * DMODEL];
__device__ float g_attn[MROWS * DMODEL];

// ---------------- tf32 helpers ----------------
__device__ __forceinline__ unsigned f2tf(float f) {
    unsigned u; asm("cvt.rna.tf32.f32 %0, %1;" : "=r"(u) : "f"(f)); return u;
}
__device__ __forceinline__ uint4 cvt4(float4 v) {
    uint4 u; u.x = f2tf(v.x); u.y = f2tf(v.y); u.z = f2tf(v.z); u.w = f2tf(v.w); return u;
}
__device__ __forceinline__ void mma_tf32(float c[4], unsigned a0, unsigned a1, unsigned a2, unsigned a3,
                                         unsigned b0, unsigned b1) {
    asm volatile(
        "mma.sync.aligned.m16n8k8.row.col.f32.tf32.tf32.f32 "
        "{%0,%1,%2,%3},{%4,%5,%6,%7},{%8,%9},{%0,%1,%2,%3};"
        : "+f"(c[0]), "+f"(c[1]), "+f"(c[2]), "+f"(c[3])
        : "r"(a0), "r"(a1), "r"(a2), "r"(a3), "r"(b0), "r"(b1));
}

// ---------------- block reduction (sum, sumsq), 256 threads ----------------
__device__ __forceinline__ float2 block_reduce2(float s, float q, float* sh) {
    #pragma unroll
    for (int o = 16; o; o >>= 1) {
        s += __shfl_xor_sync(0xffffffffu, s, o);
        q += __shfl_xor_sync(0xffffffffu, q, o);
    }
    int w = threadIdx.x >> 5;
    if ((threadIdx.x & 31) == 0) { sh[w] = s; sh[8 + w] = q; }
    __syncthreads();
    if (threadIdx.x < 32) {
        s = (threadIdx.x < 8) ? sh[threadIdx.x] : 0.f;
        q = (threadIdx.x < 8) ? sh[8 + threadIdx.x] : 0.f;
        #pragma unroll
        for (int o = 4; o; o >>= 1) {
            s += __shfl_xor_sync(0xffffffffu, s, o);
            q += __shfl_xor_sync(0xffffffffu, q, o);
        }
        if (threadIdx.x == 0) { sh[16] = s; sh[17] = q; }
    }
    __syncthreads();
    return make_float2(sh[16], sh[17]);
}

// ---------------- fused dual pre-LN ----------
__global__ void __launch_bounds__(256) prenorm_kernel(
    const float* __restrict__ x,
    const float* __restrict__ pg, const float* __restrict__ pb,
    const float* __restrict__ kg, const float* __restrict__ kb,
    float* __restrict__ xq, float* __restrict__ xkv)
{
    __shared__ float sh[18];
    int row = blockIdx.x;
    const float* xr = x + (size_t)row * DMODEL;
    float s = 0.f, q = 0.f;
    #pragma unroll
    for (int i = threadIdx.x; i < DMODEL; i += 256) { float v = xr[i]; s += v; q += v * v; }
    float2 r = block_reduce2(s, q, sh);
    float mu = r.x * (1.f / DMODEL);
    float var = r.y * (1.f / DMODEL) - mu * mu;
    float inv = rsqrtf(var + EPS);
    #pragma unroll
    for (int i = threadIdx.x; i < DMODEL; i += 256) {
        float n = (xr[i] - mu) * inv;
        xq [(size_t)row * DMODEL + i] = n * pg[i] + pb[i];
        xkv[(size_t)row * DMODEL + i] = n * kg[i] + kb[i];
    }
}

// ---------------- generic row LN ----------------
__global__ void __launch_bounds__(256) ln_kernel(
    const float* __restrict__ x, const float* __restrict__ g,
    const float* __restrict__ b, float* __restrict__ y, int N)
{
    __shared__ float sh[18];
    int row = blockIdx.x;
    const float* xr = x + (size_t)row * N;
    float s = 0.f, q = 0.f;
    for (int i = threadIdx.x; i < N; i += 256) { float v = xr[i]; s += v; q += v * v; }
    float2 r = block_reduce2(s, q, sh);
    float mu = r.x / N;
    float var = r.y / N - mu * mu;
    float inv = rsqrtf(var + EPS);
    for (int i = threadIdx.x; i < N; i += 256)
        y[(size_t)row * N + i] = (xr[i] - mu) * inv * g[i] + b[i];
}

// ---------------- tf32 tensor-core GEMM ------------------------------------
// C[M,N] = alpha * A[M,K] @ (TB ? B^T : B),  BM=BN=128, BK=32, 256 threads.
// A smem layout: k-group-of-4:  As[(k>>2)*516 + m*4 + (k&3)]  (conflict-free
// frag reads: bank=4g+t; conflict-free uint4 stores).
// B smem layout: Bs[k*136 + n]  (reads bank=8t+g; vector stores conflict-free).
#define GBM 128
#define GBN 128
#define GBK 32
#define ASTRIDE 516
#define BSTRIDE 136

template <bool TB>
__global__ void __launch_bounds__(256) gemm_tf32(
    const float* __restrict__ A, const float* __restrict__ B,
    float* __restrict__ C, int N, int K, float alpha)
{
    __shared__ unsigned As[8 * ASTRIDE];
    __shared__ unsigned Bs[GBK * BSTRIDE];

    int tid = threadIdx.x;
    int m0 = blockIdx.y * GBM, n0 = blockIdx.x * GBN;
    int warp = tid >> 5, lane = tid & 31;
    int g = lane >> 2, t = lane & 3;
    int wm = (warp & 1) * 64, wn = (warp >> 1) * 32;

    int ar = tid >> 3;      // A: row within tile (+32*i), col4 = tid&7
    int ac4 = tid & 7;
    int br = tid >> 5;      // B(!TB): k row (+8*i), col4 = tid&31
    int bc4 = tid & 31;
    int tn = tid >> 3;      // B(TB): n (+32*i), k4 = tid&7
    int tk4 = tid & 7;

    float4 ra[4], rb[4];

    auto loadT = [&](int k0) {
        #pragma unroll
        for (int i = 0; i < 4; i++)
            ra[i] = *(const float4*)&A[(size_t)(m0 + ar + 32 * i) * K + k0 + ac4 * 4];
        if (!TB) {
            #pragma unroll
            for (int i = 0; i < 4; i++)
                rb[i] = *(const float4*)&B[(size_t)(k0 + br + 8 * i) * N + n0 + bc4 * 4];
        } else {
            #pragma unroll
            for (int i = 0; i < 4; i++)
                rb[i] = *(const float4*)&B[(size_t)(n0 + tn + 32 * i) * K + k0 + tk4 * 4];
        }
    };
    auto storeT = [&]() {
        #pragma unroll
        for (int i = 0; i < 4; i++)
            *(uint4*)&As[ac4 * ASTRIDE + (ar + 32 * i) * 4] = cvt4(ra[i]);
        if (!TB) {
            #pragma unroll
            for (int i = 0; i < 4; i++)
                *(uint4*)&Bs[(br + 8 * i) * BSTRIDE + bc4 * 4] = cvt4(rb[i]);
        } else {
            #pragma unroll
            for (int i = 0; i < 4; i++) {
                int n = tn + 32 * i;
                Bs[(tk4 * 4 + 0) * BSTRIDE + n] = f2tf(rb[i].x);
                Bs[(tk4 * 4 + 1) * BSTRIDE + n] = f2tf(rb[i].y);
                Bs[(tk4 * 4 + 2) * BSTRIDE + n] = f2tf(rb[i].z);
                Bs[(tk4 * 4 + 3) * BSTRIDE + n] = f2tf(rb[i].w);
            }
        }
    };

    float c[4][4][4] = {};

    loadT(0);
    storeT();
    __syncthreads();

    for (int k0 = GBK; ; k0 += GBK) {
        bool more = k0 < K;
        if (more) loadT(k0);

        #pragma unroll
        for (int ks = 0; ks < GBK; ks += 8) {
            unsigned bf[4][2];
            #pragma unroll
            for (int nf = 0; nf < 4; nf++) {
                bf[nf][0] = Bs[(ks + t) * BSTRIDE + wn + nf * 8 + g];
                bf[nf][1] = Bs[(ks + t + 4) * BSTRIDE + wn + nf * 8 + g];
            }
            #pragma unroll
            for (int mf = 0; mf < 4; mf++) {
                int mb = wm + mf * 16 + g;
                int grp = ks >> 2;
                unsigned a0 = As[grp * ASTRIDE + mb * 4 + t];
                unsigned a1 = As[grp * ASTRIDE + (mb + 8) * 4 + t];
                unsigned a2 = As[(grp + 1) * ASTRIDE + mb * 4 + t];
                unsigned a3 = As[(grp + 1) * ASTRIDE + (mb + 8) * 4 + t];
                #pragma unroll
                for (int nf = 0; nf < 4; nf++)
                    mma_tf32(c[mf][nf], a0, a1, a2, a3, bf[nf][0], bf[nf][1]);
            }
        }
        if (!more) break;
        __syncthreads();
        storeT();
        __syncthreads();
    }

    // epilogue
    #pragma unroll
    for (int mf = 0; mf < 4; mf++) {
        int r0 = m0 + wm + mf * 16 + g;
        #pragma unroll
        for (int nf = 0; nf < 4; nf++) {
            int cc = n0 + wn + nf * 8 + 2 * t;
            float2 lo = make_float2(alpha * c[mf][nf][0], alpha * c[mf][nf][1]);
            float2 hi = make_float2(alpha * c[mf][nf][2], alpha * c[mf][nf][3]);
            *(float2*)&C[(size_t)r0 * N + cc] = lo;
            *(float2*)&C[(size_t)(r0 + 8) * N + cc] = hi;
        }
    }
}

// ---------------- causal flash attention, 64-query tiles, fp32 --------------
__global__ void __launch_bounds__(256) attn_kernel(
    const float* __restrict__ Q, const float* __restrict__ KV, float* __restrict__ O)
{
    __shared__ __align__(16) float Qs[64][64]; // [d][row]
    __shared__ __align__(16) float KP[64][64]; // K: [d][col] ; P: [row][k]
    __shared__ __align__(16) float Vs[64][64]; // [k][d]

    int tid = threadIdx.x;
    int tx = tid & 15, ty = tid >> 4;
    int qt = blockIdx.x, h = blockIdx.y, b = blockIdx.z;

    #pragma unroll
    for (int it = 0; it < 4; it++) {
        int idx = tid + it * 256;
        int r = idx >> 4, d4 = idx & 15;
        float4 qv = *(const float4*)&Q[((size_t)(b * SEQ + qt * 64 + r)) * DMODEL + h * DH + d4 * 4];
        Qs[d4 * 4 + 0][r] = qv.x; Qs[d4 * 4 + 1][r] = qv.y;
        Qs[d4 * 4 + 2][r] = qv.z; Qs[d4 * 4 + 3][r] = qv.w;
    }

    float m[4], l[4], o[4][4];
    #pragma unroll
    for (int i = 0; i < 4; i++) {
        m[i] = -INFINITY; l[i] = 0.f;
        #pragma unroll
        for (int j = 0; j < 4; j++) o[i][j] = 0.f;
    }
    __syncthreads();

    for (int ch = 0; ch <= qt; ch++) {
        #pragma unroll
        for (int it = 0; it < 4; it++) {
            int idx = tid + it * 256;
            int r = idx >> 4, d4 = idx & 15;
            size_t base = ((size_t)(b * SEQ + ch * 64 + r)) * (2 * DMODEL) + h * DH + d4 * 4;
            float4 kv = *(const float4*)&KV[base];
            KP[d4 * 4 + 0][r] = kv.x; KP[d4 * 4 + 1][r] = kv.y;
            KP[d4 * 4 + 2][r] = kv.z; KP[d4 * 4 + 3][r] = kv.w;
            float4 vv = *(const float4*)&KV[base + DMODEL];
            *(float4*)&Vs[r][d4 * 4] = vv;
        }
        __syncthreads();

        float s[4][4] = {};
        #pragma unroll
        for (int d = 0; d < 64; d++) {
            float4 a = *(float4*)&Qs[d][ty * 4];
            float4 k = *(float4*)&KP[d][tx * 4];
            s[0][0] += a.x * k.x; s[0][1] += a.x * k.y; s[0][2] += a.x * k.z; s[0][3] += a.x * k.w;
            s[1][0] += a.y * k.x; s[1][1] += a.y * k.y; s[1][2] += a.y * k.z; s[1][3] += a.y * k.w;
            s[2][0] += a.z * k.x; s[2][1] += a.z * k.y; s[2][2] += a.z * k.z; s[2][3] += a.z * k.w;
            s[3][0] += a.w * k.x; s[3][1] += a.w * k.y; s[3][2] += a.w * k.z; s[3][3] += a.w * k.w;
        }

        if (ch == qt) {
            #pragma unroll
            for (int i = 0; i < 4; i++)
                #pragma unroll
                for (int j = 0; j < 4; j++)
                    if (tx * 4 + j > ty * 4 + i) s[i][j] = -1e30f;
        }

        float li[4], sc[4];
        #pragma unroll
        for (int i = 0; i < 4; i++) {
            float mi = fmaxf(fmaxf(s[i][0], s[i][1]), fmaxf(s[i][2], s[i][3]));
            #pragma unroll
            for (int off = 8; off; off >>= 1)
                mi = fmaxf(mi, __shfl_xor_sync(0xffffffffu, mi, off));
            float mn = fmaxf(m[i], mi);
            sc[i] = __expf(m[i] - mn);
            m[i] = mn;
            float acc = 0.f;
            #pragma unroll
            for (int j = 0; j < 4; j++) { s[i][j] = __expf(s[i][j] - mn); acc += s[i][j]; }
            #pragma unroll
            for (int off = 8; off; off >>= 1)
                acc += __shfl_xor_sync(0xffffffffu, acc, off);
            li[i] = acc;
            l[i] = l[i] * sc[i] + li[i];
            #pragma unroll
            for (int j = 0; j < 4; j++) o[i][j] *= sc[i];
        }

        __syncthreads();
        #pragma unroll
        for (int i = 0; i < 4; i++)
            #pragma unroll
            for (int j = 0; j < 4; j++)
                KP[ty * 4 + i][tx * 4 + j] = s[i][j];
        __syncthreads();

        #pragma unroll
        for (int k = 0; k < 64; k++) {
            float4 v = *(float4*)&Vs[k][tx * 4];
            #pragma unroll
            for (int i = 0; i < 4; i++) {
                float p = KP[ty * 4 + i][k];
                o[i][0] += p * v.x; o[i][1] += p * v.y;
                o[i][2] += p * v.z; o[i][3] += p * v.w;
            }
        }
        __syncthreads();
    }

    #pragma unroll
    for (int i = 0; i < 4; i++) {
        float inv = 1.f / l[i];
        #pragma unroll
        for (int j = 0; j < 4; j++)
            O[((size_t)(b * SEQ + qt * 64 + ty * 4 + i)) * DMODEL + h * DH + tx * 4 + j] = o[i][j] * inv;
    }
}

// ---------------- launch ----------------
extern "C" void kernel_launch(void* const* d_in, const int* in_sizes, int n_in,
                              void* d_out, int out_size)
{
    const float* x     = (const float*)d_in[0];
    const float* W_dq  = (const float*)d_in[1];
    const float* W_uq  = (const float*)d_in[2];
    const float* q_g   = (const float*)d_in[3];
    const float* q_b   = (const float*)d_in[4];
    const float* W_dkv = (const float*)d_in[5];
    const float* W_ukv = (const float*)d_in[6];
    const float* kv_g  = (const float*)d_in[7];
    const float* kv_b  = (const float*)d_in[8];
    const float* pq_g  = (const float*)d_in[9];
    const float* pq_b  = (const float*)d_in[10];
    const float* pk_g  = (const float*)d_in[11];
    const float* pk_b  = (const float*)d_in[12];
    const float* wo    = (const float*)d_in[13];
    float* out = (float*)d_out;

    float *xq, *xkv, *tq, *cq, *Qp, *tkv, *ckv, *KV, *attn;
    cudaGetSymbolAddress((void**)&xq,   g_xq);
    cudaGetSymbolAddress((void**)&xkv,  g_xkv);
    cudaGetSymbolAddress((void**)&tq,   g_tq);
    cudaGetSymbolAddress((void**)&cq,   g_cq);
    cudaGetSymbolAddress((void**)&Qp,   g_Q);
    cudaGetSymbolAddress((void**)&tkv,  g_tkv);
    cudaGetSymbolAddress((void**)&ckv,  g_ckv);
    cudaGetSymbolAddress((void**)&KV,   g_KV);
    cudaGetSymbolAddress((void**)&attn, g_attn);

    // 1. fused dual pre-LN (shared mean/var)
    prenorm_kernel<<<MROWS, 256>>>(x, pq_g, pq_b, pk_g, pk_b, xq, xkv);
    // 2-4. Q path
    gemm_tf32<false><<<dim3(QPROJ / GBN, MROWS / GBM), 256>>>(xq, W_dq, tq, QPROJ, DMODEL, 1.f);
    ln_kernel<<<MROWS, 256>>>(tq, q_g, q_b, cq, QPROJ);
    gemm_tf32<false><<<dim3(DMODEL / GBN, MROWS / GBM), 256>>>(cq, W_uq, Qp, DMODEL, QPROJ, 0.125f);
    // 5-7. KV path
    gemm_tf32<false><<<dim3(KVPROJ / GBN, MROWS / GBM), 256>>>(xkv, W_dkv, tkv, KVPROJ, DMODEL, 1.f);
    ln_kernel<<<MROWS, 256>>>(tkv, kv_g, kv_b, ckv, KVPROJ);
    gemm_tf32<false><<<dim3(2 * DMODEL / GBN, MROWS / GBM), 256>>>(ckv, W_ukv, KV, 2 * DMODEL, KVPROJ, 1.f);
    // 8. causal flash attention
    attn_kernel<<<dim3(SEQ / 64, NH, BATCH), 256>>>(Qp, KV, attn);
    // 9. output projection: attn @ wo^T
    gemm_tf32<true><<<dim3(DMODEL / GBN, MROWS / GBM), 256>>>(attn, wo, out, DMODEL, DMODEL, 1.f);
}

// round 3
// speedup vs baseline: 5.1226x; 1.7286x over previous
#include <cuda_runtime.h>
#include <math.h>

#define MROWS 4096
#define DMODEL 1024
#define QPROJ 512
#define KVPROJ 1024
#define NH 16
#define DH 64
#define SEQ 2048
#define BATCH 2
#define EPS 1e-5f

// ---------------- scratch (no allocations allowed) ----------------
__device__ float g_xq  [MROWS * DMODEL];
__device__ float g_xkv [MROWS * DMODEL];
__device__ float g_tq  [MROWS * QPROJ];
__device__ float g_cq  [MROWS * QPROJ];
__device__ float g_Q   [MROWS * DMODEL];
__device__ float g_tkv [MROWS * KVPROJ];
__device__ float g_ckv [MROWS * KVPROJ];
__device__ float g_KV  [MROWS * 2 * DMODEL];
__device__ float g_attn[MROWS * DMODEL];

// ---------------- tf32 helpers ----------------
__device__ __forceinline__ unsigned f2tf(float f) {
    unsigned u; asm("cvt.rna.tf32.f32 %0, %1;" : "=r"(u) : "f"(f)); return u;
}
__device__ __forceinline__ uint4 cvt4(float4 v) {
    uint4 u; u.x = f2tf(v.x); u.y = f2tf(v.y); u.z = f2tf(v.z); u.w = f2tf(v.w); return u;
}
__device__ __forceinline__ void mma_tf32(float c[4], unsigned a0, unsigned a1, unsigned a2, unsigned a3,
                                         unsigned b0, unsigned b1) {
    asm volatile(
        "mma.sync.aligned.m16n8k8.row.col.f32.tf32.tf32.f32 "
        "{%0,%1,%2,%3},{%4,%5,%6,%7},{%8,%9},{%0,%1,%2,%3};"
        : "+f"(c[0]), "+f"(c[1]), "+f"(c[2]), "+f"(c[3])
        : "r"(a0), "r"(a1), "r"(a2), "r"(a3), "r"(b0), "r"(b1));
}

// ---------------- block reduction (sum, sumsq), 256 threads ----------------
__device__ __forceinline__ float2 block_reduce2(float s, float q, float* sh) {
    #pragma unroll
    for (int o = 16; o; o >>= 1) {
        s += __shfl_xor_sync(0xffffffffu, s, o);
        q += __shfl_xor_sync(0xffffffffu, q, o);
    }
    int w = threadIdx.x >> 5;
    if ((threadIdx.x & 31) == 0) { sh[w] = s; sh[8 + w] = q; }
    __syncthreads();
    if (threadIdx.x < 32) {
        s = (threadIdx.x < 8) ? sh[threadIdx.x] : 0.f;
        q = (threadIdx.x < 8) ? sh[8 + threadIdx.x] : 0.f;
        #pragma unroll
        for (int o = 4; o; o >>= 1) {
            s += __shfl_xor_sync(0xffffffffu, s, o);
            q += __shfl_xor_sync(0xffffffffu, q, o);
        }
        if (threadIdx.x == 0) { sh[16] = s; sh[17] = q; }
    }
    __syncthreads();
    return make_float2(sh[16], sh[17]);
}

// ---------------- fused dual pre-LN ----------
__global__ void __launch_bounds__(256) prenorm_kernel(
    const float* __restrict__ x,
    const float* __restrict__ pg, const float* __restrict__ pb,
    const float* __restrict__ kg, const float* __restrict__ kb,
    float* __restrict__ xq, float* __restrict__ xkv)
{
    __shared__ float sh[18];
    int row = blockIdx.x;
    const float* xr = x + (size_t)row * DMODEL;
    float s = 0.f, q = 0.f;
    #pragma unroll
    for (int i = threadIdx.x; i < DMODEL; i += 256) { float v = xr[i]; s += v; q += v * v; }
    float2 r = block_reduce2(s, q, sh);
    float mu = r.x * (1.f / DMODEL);
    float var = r.y * (1.f / DMODEL) - mu * mu;
    float inv = rsqrtf(var + EPS);
    #pragma unroll
    for (int i = threadIdx.x; i < DMODEL; i += 256) {
        float n = (xr[i] - mu) * inv;
        xq [(size_t)row * DMODEL + i] = n * pg[i] + pb[i];
        xkv[(size_t)row * DMODEL + i] = n * kg[i] + kb[i];
    }
}

// ---------------- generic row LN ----------------
__global__ void __launch_bounds__(256) ln_kernel(
    const float* __restrict__ x, const float* __restrict__ g,
    const float* __restrict__ b, float* __restrict__ y, int N)
{
    __shared__ float sh[18];
    int row = blockIdx.x;
    const float* xr = x + (size_t)row * N;
    float s = 0.f, q = 0.f;
    for (int i = threadIdx.x; i < N; i += 256) { float v = xr[i]; s += v; q += v * v; }
    float2 r = block_reduce2(s, q, sh);
    float mu = r.x / N;
    float var = r.y / N - mu * mu;
    float inv = rsqrtf(var + EPS);
    for (int i = threadIdx.x; i < N; i += 256)
        y[(size_t)row * N + i] = (xr[i] - mu) * inv * g[i] + b[i];
}

// ---------------- tf32 tensor-core GEMM (unchanged from R2) -----------------
#define GBM 128
#define GBN 128
#define GBK 32
#define ASTRIDE 516
#define BSTRIDE 136

template <bool TB>
__global__ void __launch_bounds__(256) gemm_tf32(
    const float* __restrict__ A, const float* __restrict__ B,
    float* __restrict__ C, int N, int K, float alpha)
{
    __shared__ unsigned As[8 * ASTRIDE];
    __shared__ unsigned Bs[GBK * BSTRIDE];

    int tid = threadIdx.x;
    int m0 = blockIdx.y * GBM, n0 = blockIdx.x * GBN;
    int warp = tid >> 5, lane = tid & 31;
    int g = lane >> 2, t = lane & 3;
    int wm = (warp & 1) * 64, wn = (warp >> 1) * 32;

    int ar = tid >> 3, ac4 = tid & 7;
    int br = tid >> 5, bc4 = tid & 31;
    int tn = tid >> 3, tk4 = tid & 7;

    float4 ra[4], rb[4];

    auto loadT = [&](int k0) {
        #pragma unroll
        for (int i = 0; i < 4; i++)
            ra[i] = *(const float4*)&A[(size_t)(m0 + ar + 32 * i) * K + k0 + ac4 * 4];
        if (!TB) {
            #pragma unroll
            for (int i = 0; i < 4; i++)
                rb[i] = *(const float4*)&B[(size_t)(k0 + br + 8 * i) * N + n0 + bc4 * 4];
        } else {
            #pragma unroll
            for (int i = 0; i < 4; i++)
                rb[i] = *(const float4*)&B[(size_t)(n0 + tn + 32 * i) * K + k0 + tk4 * 4];
        }
    };
    auto storeT = [&]() {
        #pragma unroll
        for (int i = 0; i < 4; i++)
            *(uint4*)&As[ac4 * ASTRIDE + (ar + 32 * i) * 4] = cvt4(ra[i]);
        if (!TB) {
            #pragma unroll
            for (int i = 0; i < 4; i++)
                *(uint4*)&Bs[(br + 8 * i) * BSTRIDE + bc4 * 4] = cvt4(rb[i]);
        } else {
            #pragma unroll
            for (int i = 0; i < 4; i++) {
                int n = tn + 32 * i;
                Bs[(tk4 * 4 + 0) * BSTRIDE + n] = f2tf(rb[i].x);
                Bs[(tk4 * 4 + 1) * BSTRIDE + n] = f2tf(rb[i].y);
                Bs[(tk4 * 4 + 2) * BSTRIDE + n] = f2tf(rb[i].z);
                Bs[(tk4 * 4 + 3) * BSTRIDE + n] = f2tf(rb[i].w);
            }
        }
    };

    float c[4][4][4] = {};

    loadT(0);
    storeT();
    __syncthreads();

    for (int k0 = GBK; ; k0 += GBK) {
        bool more = k0 < K;
        if (more) loadT(k0);

        #pragma unroll
        for (int ks = 0; ks < GBK; ks += 8) {
            unsigned bf[4][2];
            #pragma unroll
            for (int nf = 0; nf < 4; nf++) {
                bf[nf][0] = Bs[(ks + t) * BSTRIDE + wn + nf * 8 + g];
                bf[nf][1] = Bs[(ks + t + 4) * BSTRIDE + wn + nf * 8 + g];
            }
            #pragma unroll
            for (int mf = 0; mf < 4; mf++) {
                int mb = wm + mf * 16 + g;
                int grp = ks >> 2;
                unsigned a0 = As[grp * ASTRIDE + mb * 4 + t];
                unsigned a1 = As[grp * ASTRIDE + (mb + 8) * 4 + t];
                unsigned a2 = As[(grp + 1) * ASTRIDE + mb * 4 + t];
                unsigned a3 = As[(grp + 1) * ASTRIDE + (mb + 8) * 4 + t];
                #pragma unroll
                for (int nf = 0; nf < 4; nf++)
                    mma_tf32(c[mf][nf], a0, a1, a2, a3, bf[nf][0], bf[nf][1]);
            }
        }
        if (!more) break;
        __syncthreads();
        storeT();
        __syncthreads();
    }

    #pragma unroll
    for (int mf = 0; mf < 4; mf++) {
        int r0 = m0 + wm + mf * 16 + g;
        #pragma unroll
        for (int nf = 0; nf < 4; nf++) {
            int cc = n0 + wn + nf * 8 + 2 * t;
            float2 lo = make_float2(alpha * c[mf][nf][0], alpha * c[mf][nf][1]);
            float2 hi = make_float2(alpha * c[mf][nf][2], alpha * c[mf][nf][3]);
            *(float2*)&C[(size_t)r0 * N + cc] = lo;
            *(float2*)&C[(size_t)(r0 + 8) * N + cc] = hi;
        }
    }
}

// ---------------- tensor-core causal flash attention ------------------------
// 128 threads (4 warps), 64-query tile per block; warp w owns rows w*16..w*16+15.
// Smem: QP buf [64][68] (Q then reused per-warp for P), K [64][76], V [64][76].
// Stride 76 (mod 32 = 12) makes both B-frag patterns conflict-free; stride 68
// (mod 32 = 4) makes A-frag reads conflict-free.
#define QP_STR 68
#define KV_STR 76
#define ATT_SMEM ((64 * QP_STR + 2 * 64 * KV_STR) * 4)

extern __shared__ float att_sm[];

__global__ void __launch_bounds__(128) attn_tc_kernel(
    const float* __restrict__ Q, const float* __restrict__ KV, float* __restrict__ O)
{
    float* sQP = att_sm;                    // 64*68
    float* sK  = sQP + 64 * QP_STR;         // 64*76
    float* sV  = sK  + 64 * KV_STR;         // 64*76

    int tid = threadIdx.x, warp = tid >> 5, lane = tid & 31;
    int g = lane >> 2, t = lane & 3;
    int wm = warp * 16;
    int qt = (int)gridDim.x - 1 - (int)blockIdx.x;   // heavy tiles first
    int h = blockIdx.y, b = blockIdx.z;
    int qrow0 = qt * 64;

    // ---- load Q tile -> smem (natural [q][d]) ----
    #pragma unroll
    for (int it = 0; it < 8; it++) {
        int idx = tid + it * 128;
        int r = idx >> 4, c4 = idx & 15;
        float4 v = *(const float4*)&Q[((size_t)(b * SEQ + qrow0 + r)) * DMODEL + h * DH + c4 * 4];
        *(float4*)&sQP[r * QP_STR + c4 * 4] = v;
    }
    __syncthreads();

    // ---- build Q A-fragments (registers), raw fp32 bits as tf32 operand ----
    unsigned qa[8][4];
    #pragma unroll
    for (int ks = 0; ks < 8; ks++) {
        qa[ks][0] = __float_as_uint(sQP[(wm + g)     * QP_STR + ks * 8 + t]);
        qa[ks][1] = __float_as_uint(sQP[(wm + g + 8) * QP_STR + ks * 8 + t]);
        qa[ks][2] = __float_as_uint(sQP[(wm + g)     * QP_STR + ks * 8 + t + 4]);
        qa[ks][3] = __float_as_uint(sQP[(wm + g + 8) * QP_STR + ks * 8 + t + 4]);
    }
    __syncthreads();   // QP buffer now free for P

    float m0 = -INFINITY, m1 = -INFINITY, l0 = 0.f, l1 = 0.f;
    float co[8][4] = {};

    for (int ch = 0; ch <= qt; ch++) {
        // ---- load K/V chunk (raw fp32; 16-byte stores, stride 76 aligned) ----
        #pragma unroll
        for (int it = 0; it < 8; it++) {
            int idx = tid + it * 128;
            int r = idx >> 4, c4 = idx & 15;
            size_t base = ((size_t)(b * SEQ + ch * 64 + r)) * (2 * DMODEL) + h * DH + c4 * 4;
            float4 k4 = *(const float4*)&KV[base];
            float4 v4 = *(const float4*)&KV[base + DMODEL];
            *(float4*)&sK[r * KV_STR + c4 * 4] = k4;
            *(float4*)&sV[r * KV_STR + c4 * 4] = v4;
        }
        __syncthreads();

        // ---- S = Q K^T ----
        float s[8][4] = {};
        #pragma unroll
        for (int ks = 0; ks < 8; ks++) {
            #pragma unroll
            for (int nf = 0; nf < 8; nf++) {
                unsigned b0 = __float_as_uint(sK[(nf * 8 + g) * KV_STR + ks * 8 + t]);
                unsigned b1 = __float_as_uint(sK[(nf * 8 + g) * KV_STR + ks * 8 + t + 4]);
                mma_tf32(s[nf], qa[ks][0], qa[ks][1], qa[ks][2], qa[ks][3], b0, b1);
            }
        }

        // ---- causal mask (diagonal chunk only) ----
        if (ch == qt) {
            int r0 = wm + g, r1 = wm + g + 8;
            #pragma unroll
            for (int nf = 0; nf < 8; nf++) {
                int col = nf * 8 + 2 * t;
                if (col     > r0) s[nf][0] = -1e30f;
                if (col + 1 > r0) s[nf][1] = -1e30f;
                if (col     > r1) s[nf][2] = -1e30f;
                if (col + 1 > r1) s[nf][3] = -1e30f;
            }
        }

        // ---- online softmax (quad-lane reductions) ----
        float mx0 = -1e30f, mx1 = -1e30f;
        #pragma unroll
        for (int nf = 0; nf < 8; nf++) {
            mx0 = fmaxf(mx0, fmaxf(s[nf][0], s[nf][1]));
            mx1 = fmaxf(mx1, fmaxf(s[nf][2], s[nf][3]));
        }
        mx0 = fmaxf(mx0, __shfl_xor_sync(0xffffffffu, mx0, 1));
        mx0 = fmaxf(mx0, __shfl_xor_sync(0xffffffffu, mx0, 2));
        mx1 = fmaxf(mx1, __shfl_xor_sync(0xffffffffu, mx1, 1));
        mx1 = fmaxf(mx1, __shfl_xor_sync(0xffffffffu, mx1, 2));
        float nm0 = fmaxf(m0, mx0), nm1 = fmaxf(m1, mx1);
        float sc0 = __expf(m0 - nm0), sc1 = __expf(m1 - nm1);
        m0 = nm0; m1 = nm1;
        float sum0 = 0.f, sum1 = 0.f;
        #pragma unroll
        for (int nf = 0; nf < 8; nf++) {
            s[nf][0] = __expf(s[nf][0] - m0); sum0 += s[nf][0];
            s[nf][1] = __expf(s[nf][1] - m0); sum0 += s[nf][1];
            s[nf][2] = __expf(s[nf][2] - m1); sum1 += s[nf][2];
            s[nf][3] = __expf(s[nf][3] - m1); sum1 += s[nf][3];
        }
        sum0 += __shfl_xor_sync(0xffffffffu, sum0, 1);
        sum0 += __shfl_xor_sync(0xffffffffu, sum0, 2);
        sum1 += __shfl_xor_sync(0xffffffffu, sum1, 1);
        sum1 += __shfl_xor_sync(0xffffffffu, sum1, 2);
        l0 = l0 * sc0 + sum0;
        l1 = l1 * sc1 + sum1;
        #pragma unroll
        for (int nf = 0; nf < 8; nf++) {
            co[nf][0] *= sc0; co[nf][1] *= sc0;
            co[nf][2] *= sc1; co[nf][3] *= sc1;
        }

        // ---- write P (tf32, rna) to per-warp rows of QP buffer ----
        #pragma unroll
        for (int nf = 0; nf < 8; nf++) {
            int cbase = nf * 8 + 2 * t;
            sQP[(wm + g)     * QP_STR + cbase]     = __uint_as_float(f2tf(s[nf][0]));
            sQP[(wm + g)     * QP_STR + cbase + 1] = __uint_as_float(f2tf(s[nf][1]));
            sQP[(wm + g + 8) * QP_STR + cbase]     = __uint_as_float(f2tf(s[nf][2]));
            sQP[(wm + g + 8) * QP_STR + cbase + 1] = __uint_as_float(f2tf(s[nf][3]));
        }
        __syncwarp();

        // ---- O += P V ----
        #pragma unroll
        for (int ks = 0; ks < 8; ks++) {
            unsigned pa0 = __float_as_uint(sQP[(wm + g)     * QP_STR + ks * 8 + t]);
            unsigned pa1 = __float_as_uint(sQP[(wm + g + 8) * QP_STR + ks * 8 + t]);
            unsigned pa2 = __float_as_uint(sQP[(wm + g)     * QP_STR + ks * 8 + t + 4]);
            unsigned pa3 = __float_as_uint(sQP[(wm + g + 8) * QP_STR + ks * 8 + t + 4]);
            #pragma unroll
            for (int nf = 0; nf < 8; nf++) {
                unsigned b0 = f2tf(sV[(ks * 8 + t)     * KV_STR + nf * 8 + g]);
                unsigned b1 = f2tf(sV[(ks * 8 + t + 4) * KV_STR + nf * 8 + g]);
                mma_tf32(co[nf], pa0, pa1, pa2, pa3, b0, b1);
            }
        }
        __syncthreads();   // before next chunk overwrites sK/sV
    }

    // ---- epilogue ----
    float inv0 = 1.f / l0, inv1 = 1.f / l1;
    size_t row0 = (size_t)(b * SEQ + qrow0 + wm + g) * DMODEL + h * DH;
    size_t row1 = (size_t)(b * SEQ + qrow0 + wm + g + 8) * DMODEL + h * DH;
    #pragma unroll
    for (int nf = 0; nf < 8; nf++) {
        int cbase = nf * 8 + 2 * t;
        *(float2*)&O[row0 + cbase] = make_float2(co[nf][0] * inv0, co[nf][1] * inv0);
        *(float2*)&O[row1 + cbase] = make_float2(co[nf][2] * inv1, co[nf][3] * inv1);
    }
}

// ---------------- launch ----------------
extern "C" void kernel_launch(void* const* d_in, const int* in_sizes, int n_in,
                              void* d_out, int out_size)
{
    const float* x     = (const float*)d_in[0];
    const float* W_dq  = (const float*)d_in[1];
    const float* W_uq  = (const float*)d_in[2];
    const float* q_g   = (const float*)d_in[3];
    const float* q_b   = (const float*)d_in[4];
    const float* W_dkv = (const float*)d_in[5];
    const float* W_ukv = (const float*)d_in[6];
    const float* kv_g  = (const float*)d_in[7];
    const float* kv_b  = (const float*)d_in[8];
    const float* pq_g  = (const float*)d_in[9];
    const float* pq_b  = (const float*)d_in[10];
    const float* pk_g  = (const float*)d_in[11];
    const float* pk_b  = (const float*)d_in[12];
    const float* wo    = (const float*)d_in[13];
    float* out = (float*)d_out;

    float *xq, *xkv, *tq, *cq, *Qp, *tkv, *ckv, *KV, *attn;
    cudaGetSymbolAddress((void**)&xq,   g_xq);
    cudaGetSymbolAddress((void**)&xkv,  g_xkv);
    cudaGetSymbolAddress((void**)&tq,   g_tq);
    cudaGetSymbolAddress((void**)&cq,   g_cq);
    cudaGetSymbolAddress((void**)&Qp,   g_Q);
    cudaGetSymbolAddress((void**)&tkv,  g_tkv);
    cudaGetSymbolAddress((void**)&ckv,  g_ckv);
    cudaGetSymbolAddress((void**)&KV,   g_KV);
    cudaGetSymbolAddress((void**)&attn, g_attn);

    cudaFuncSetAttribute(attn_tc_kernel, cudaFuncAttributeMaxDynamicSharedMemorySize, ATT_SMEM);

    // 1. fused dual pre-LN (shared mean/var)
    prenorm_kernel<<<MROWS, 256>>>(x, pq_g, pq_b, pk_g, pk_b, xq, xkv);
    // 2-4. Q path
    gemm_tf32<false><<<dim3(QPROJ / GBN, MROWS / GBM), 256>>>(xq, W_dq, tq, QPROJ, DMODEL, 1.f);
    ln_kernel<<<MROWS, 256>>>(tq, q_g, q_b, cq, QPROJ);
    gemm_tf32<false><<<dim3(DMODEL / GBN, MROWS / GBM), 256>>>(cq, W_uq, Qp, DMODEL, QPROJ, 0.125f);
    // 5-7. KV path
    gemm_tf32<false><<<dim3(KVPROJ / GBN, MROWS / GBM), 256>>>(xkv, W_dkv, tkv, KVPROJ, DMODEL, 1.f);
    ln_kernel<<<MROWS, 256>>>(tkv, kv_g, kv_b, ckv, KVPROJ);
    gemm_tf32<false><<<dim3(2 * DMODEL / GBN, MROWS / GBM), 256>>>(ckv, W_ukv, KV, 2 * DMODEL, KVPROJ, 1.f);
    // 8. tensor-core causal flash attention
    attn_tc_kernel<<<dim3(SEQ / 64, NH, BATCH), 128, ATT_SMEM>>>(Qp, KV, attn);
    // 9. output projection: attn @ wo^T
    gemm_tf32<true><<<dim3(DMODEL / GBN, MROWS / GBM), 256>>>(attn, wo, out, DMODEL, DMODEL, 1.f);
}